// round 15
// baseline (speedup 1.0000x reference)
#include <cuda_runtime.h>
#include <cuda_fp16.h>
#include <mma.h>
#include <cstdint>
#include <math_constants.h>

using namespace nvcuda;

static constexpr int B = 8, S = 2048, D = 768;
static constexpr int M_TOT = B * S;   // 16384
static constexpr int NTILE = S / 128; // 16 key tiles per row

// ---------------------------------------------------------------------------
// Scratch (__device__ globals — allocation-free rule)
// ---------------------------------------------------------------------------
__device__ __half g_xh [(size_t)B * S * D];
__device__ __half g_xl [(size_t)B * S * D];
__device__ __half g_xTh[(size_t)B * S * D];   // [B, D, S]
__device__ __half g_Wh [D * D];
__device__ __half g_Wl [D * D];
__device__ __half g_pwh[D * D];
__device__ __half g_Wxh[(size_t)B * S * D];
__device__ __half g_Wxl[(size_t)B * S * D];
__device__ __half g_ah [(size_t)B * S * S];   // unnormalized p = exp(v - m_tile), fp16
__device__ __half g_ch [(size_t)B * S * D];
__device__ float2 g_st [(size_t)B * S * NTILE]; // per-(row,tile) partial (max, sumexp)

// ---------------------------------------------------------------------------
// helpers
// ---------------------------------------------------------------------------
__device__ __forceinline__ uint32_t smem_u32(const void* p) {
    uint32_t a;
    asm("{ .reg .u64 t; cvta.to.shared.u64 t, %1; cvt.u32.u64 %0, t; }" : "=r"(a) : "l"(p));
    return a;
}
__device__ __forceinline__ void cp16(uint32_t saddr, const void* g) {
    asm volatile("cp.async.cg.shared.global [%0], [%1], 16;" :: "r"(saddr), "l"(g));
}
__device__ __forceinline__ void cp_commit() { asm volatile("cp.async.commit_group;" ::: "memory"); }
__device__ __forceinline__ void cp_wait1()  { asm volatile("cp.async.wait_group 1;" ::: "memory"); }

__device__ __forceinline__ float wmax(float v) {
    #pragma unroll
    for (int o = 16; o > 0; o >>= 1) v = fmaxf(v, __shfl_xor_sync(0xffffffffu, v, o));
    return v;
}
__device__ __forceinline__ float wsum(float v) {
    #pragma unroll
    for (int o = 16; o > 0; o >>= 1) v += __shfl_xor_sync(0xffffffffu, v, o);
    return v;
}

// ---------------------------------------------------------------------------
// hgemm: C[M,N] = A[M,K] * B[N,K]^T  (both operands K-contiguous fp16)
// 256 threads (8 warps), BK=64, padded smem rows LDH=72 (conflict-free ldsm).
// TMv=256: CTA 256x128, warps 4x2 of 64x64 (acc 4x4)     — SP3 GEMMs, 1 CTA/SM
// TMv=128: CTA 128x128, warps 2x4 of 64x32 (acc 4x2)     — plain GEMMs, 2 CTA/SM
// SP3: 3-pass compensated product (Ah*Bh + Ah*Bl + Al*Bh).
// ASCALE: rescale landed A smem tiles by per-(row,ktile) softmax normalizer
//         (scales built from stats in the prologue; replaces finalize kernel;
//         rounding identical: float mul then __floats2half2_rn).
// EPI: 1 = split fp16 (Ch+Cl); 2 = fp16 Ch; 3 = fp32 resid + relu(C + bias);
//      4 = fused partial softmax (TMv=256 only)
// ---------------------------------------------------------------------------
static constexpr int BK  = 64;
static constexpr int TN_CTA = 128;
static constexpr int NTHR = 256;
static constexpr int LDH = 72;                        // halves per smem row
static constexpr uint32_t BT_B = TN_CTA * LDH * 2;    // 18432 bytes
static constexpr int LDS4 = 132;                      // fp32 stage stride (EPI4)

template <bool SP3, int TMv>
__device__ __forceinline__ void load_chunk(
    uint32_t sb, const __half* Ah, const __half* Al,
    const __half* Bh, const __half* Bl,
    int lda, int ldb, int rowBase, int colBase, int k0, int tid)
{
    constexpr uint32_t ATB = (uint32_t)TMv * LDH * 2;
    const uint32_t sbB = sb + (SP3 ? 2 : 1) * ATB;
    // A tiles: TMv rows x 8 granules of 16B
    #pragma unroll
    for (int i = 0; i < TMv * 8 / NTHR; ++i) {
        const int g = tid + i * NTHR;
        const int r = g >> 3;
        const int c = g & 7;
        const uint32_t off = (uint32_t)(r * (LDH * 2) + c * 16);
        const size_t ga = (size_t)(rowBase + r) * lda + k0 + c * 8;
        cp16(sb + off, Ah + ga);
        if (SP3) cp16(sb + ATB + off, Al + ga);
    }
    // B tiles: 128 rows x 8 granules = 1024
    #pragma unroll
    for (int i = 0; i < 4; ++i) {
        const int g = tid + i * NTHR;
        const int r = g >> 3;
        const int c = g & 7;
        const uint32_t off = (uint32_t)(r * (LDH * 2) + c * 16);
        const size_t gb = (size_t)(colBase + r) * ldb + k0 + c * 8;
        cp16(sbB + off, Bh + gb);
        if (SP3) cp16(sbB + BT_B + off, Bl + gb);
    }
}

template <bool SP3, int TMv>
__device__ __forceinline__ void compute_chunk(
    const __half* sm,
    wmma::fragment<wmma::accumulator, 16, 16, 16, float> acc[4][4],
    int warp_m, int warp_n)
{
    constexpr int NJV = (TMv == 256) ? 4 : 2;
    const __half* As  = sm;
    const __half* Als = sm + TMv * LDH;
    const __half* Bs  = sm + (SP3 ? 2 : 1) * TMv * LDH;
    const __half* Bls = Bs + TN_CTA * LDH;

    #pragma unroll
    for (int kk = 0; kk < BK / 16; ++kk) {
        wmma::fragment<wmma::matrix_b, 16, 16, 16, __half, wmma::col_major> bh[NJV], bl[NJV];
        wmma::fragment<wmma::matrix_a, 16, 16, 16, __half, wmma::row_major> ah[4], al[4];
        #pragma unroll
        for (int nj = 0; nj < NJV; ++nj) {
            wmma::load_matrix_sync(bh[nj], Bs + (size_t)(warp_n + nj * 16) * LDH + kk * 16, LDH);
            if (SP3)
                wmma::load_matrix_sync(bl[nj], Bls + (size_t)(warp_n + nj * 16) * LDH + kk * 16, LDH);
        }
        #pragma unroll
        for (int mi = 0; mi < 4; ++mi) {
            wmma::load_matrix_sync(ah[mi], As + (size_t)(warp_m + mi * 16) * LDH + kk * 16, LDH);
            if (SP3)
                wmma::load_matrix_sync(al[mi], Als + (size_t)(warp_m + mi * 16) * LDH + kk * 16, LDH);
        }
        #pragma unroll
        for (int mi = 0; mi < 4; ++mi)
            #pragma unroll
            for (int nj = 0; nj < NJV; ++nj)
                wmma::mma_sync(acc[mi][nj], ah[mi], bh[nj], acc[mi][nj]);
        if (SP3) {
            #pragma unroll
            for (int mi = 0; mi < 4; ++mi)
                #pragma unroll
                for (int nj = 0; nj < NJV; ++nj)
                    wmma::mma_sync(acc[mi][nj], ah[mi], bl[nj], acc[mi][nj]);
            #pragma unroll
            for (int mi = 0; mi < 4; ++mi)
                #pragma unroll
                for (int nj = 0; nj < NJV; ++nj)
                    wmma::mma_sync(acc[mi][nj], al[mi], bh[nj], acc[mi][nj]);
        }
    }
}

template <bool SP3, int EPI, int TMv, bool ASCALE>
__global__ __launch_bounds__(NTHR, (TMv == 128) ? 2 : 1)
void hgemm(const __half* __restrict__ Ah, const __half* __restrict__ Al,
           const __half* __restrict__ Bh, const __half* __restrict__ Bl,
           float* __restrict__ Cf, __half* __restrict__ Ch, __half* __restrict__ Cl,
           const float* __restrict__ bias, const float* __restrict__ resid,
           float2* __restrict__ stats,
           int lda, int ldb, int ldc, int K,
           size_t sA, size_t sB, size_t sC)
{
    extern __shared__ char smem[];
    const uint32_t sb0 = smem_u32(smem);
    constexpr uint32_t ATB = (uint32_t)TMv * LDH * 2;
    constexpr uint32_t BUF = (SP3 ? 2 : 1) * (ATB + BT_B);
    constexpr int NJV = (TMv == 256) ? 4 : 2;

    const int tid = threadIdx.x, wid = tid >> 5, lane = tid & 31;
    const int rowBase = blockIdx.y * TMv;
    const int colBase = blockIdx.x * TN_CTA;
    const int warp_m = (TMv == 256) ? (wid >> 1) * 64 : (wid >> 2) * 64;
    const int warp_n = (TMv == 256) ? (wid & 1) * 64  : (wid & 3) * 32;

    Ah += (size_t)blockIdx.z * sA;
    Bh += (size_t)blockIdx.z * sB;
    if (SP3) { Al += (size_t)blockIdx.z * sA; Bl += (size_t)blockIdx.z * sB; }

    // ASCALE prologue: per-(row, ktile) softmax scales into smem after buffers
    float* scbuf = (float*)(smem + 2 * BUF);
    if (ASCALE) {
        if (tid < TMv) {
            const int q = rowBase + tid;
            const float2* strow = stats + ((size_t)blockIdx.z * S + q) * NTILE;
            float2 t[NTILE];
            #pragma unroll
            for (int i = 0; i < NTILE; ++i) t[i] = strow[i];
            float M = t[0].x;
            #pragma unroll
            for (int i = 1; i < NTILE; ++i) M = fmaxf(M, t[i].x);
            float Z = 0.f;
            #pragma unroll
            for (int i = 0; i < NTILE; ++i) Z += t[i].y * __expf(t[i].x - M);
            const float inv = 1.0f / Z;
            #pragma unroll
            for (int i = 0; i < NTILE; ++i)
                scbuf[tid * NTILE + i] = __expf(t[i].x - M) * inv;
        }
        // first in-loop __syncthreads orders these writes before scaling reads
    }

    wmma::fragment<wmma::accumulator, 16, 16, 16, float> acc[4][4];
    #pragma unroll
    for (int mi = 0; mi < 4; ++mi)
        #pragma unroll
        for (int nj = 0; nj < NJV; ++nj)
            wmma::fill_fragment(acc[mi][nj], 0.0f);

    const int NK = K / BK;

    load_chunk<SP3, TMv>(sb0, Ah, Al, Bh, Bl, lda, ldb, rowBase, colBase, 0, tid);
    cp_commit();

    for (int ck = 0; ck < NK; ++ck) {
        if (ck + 1 < NK)
            load_chunk<SP3, TMv>(sb0 + ((ck + 1) & 1) * BUF, Ah, Al, Bh, Bl,
                                 lda, ldb, rowBase, colBase, (ck + 1) * BK, tid);
        cp_commit();
        cp_wait1();
        __syncthreads();
        if (ASCALE) {
            // rescale landed A tile rows by softmax normalizer (one ktile/chunk)
            const int kt = ck >> 1;                       // BK=64: 2 chunks/ktile
            const int r = tid >> 1;                       // 2 threads per row
            const float s = scbuf[r * NTILE + kt];
            __half2* row = (__half2*)(smem + (ck & 1) * BUF + (size_t)r * (LDH * 2))
                         + (tid & 1) * 16;
            #pragma unroll
            for (int j = 0; j < 16; ++j) {
                const float2 f = __half22float2(row[j]);
                row[j] = __floats2half2_rn(f.x * s, f.y * s);
            }
            __syncthreads();
        }
        compute_chunk<SP3, TMv>((const __half*)(smem + (ck & 1) * BUF), acc, warp_m, warp_n);
        __syncthreads();
    }

    if (EPI == 4) {
        // ---- fused partial softmax (GEMM2, TMv=256) ----
        float* stg = (float*)smem;   // 256 x 128 fp32, stride LDS4=132
        #pragma unroll
        for (int mi = 0; mi < 4; ++mi)
            #pragma unroll
            for (int nj = 0; nj < NJV; ++nj)
                wmma::store_matrix_sync(stg + (size_t)(warp_m + mi * 16) * LDS4 + warp_n + nj * 16,
                                        acc[mi][nj], LDS4, wmma::mem_row_major);
        __syncthreads();

        __half* pB = Ch + (size_t)blockIdx.z * sC;
        #pragma unroll
        for (int rr = 0; rr < 32; ++rr) {
            const int r = wid * 32 + rr;
            const int q = rowBase + r;                 // batch-local query index
            float v[4];
            #pragma unroll
            for (int k = 0; k < 4; ++k) {
                const int c = lane + 32 * k;
                float t = stg[(size_t)r * LDS4 + c];
                if (q == colBase + c) t = -CUDART_INF_F;   // mask diagonal
                v[k] = t;
            }
            float m = fmaxf(fmaxf(v[0], v[1]), fmaxf(v[2], v[3]));
            m = wmax(m);
            float e[4], zs = 0.f;
            #pragma unroll
            for (int k = 0; k < 4; ++k) { e[k] = __expf(v[k] - m); zs += e[k]; }
            const float z = wsum(zs);
            #pragma unroll
            for (int k = 0; k < 4; ++k)
                pB[(size_t)q * ldc + colBase + lane + 32 * k] = __float2half_rn(e[k]);
            if (lane == 0)
                stats[((size_t)blockIdx.z * S + q) * NTILE + (colBase >> 7)] = make_float2(m, z);
        }
        return;
    }

    // staged epilogue (EPI 1/2/3): park the TMv x 128 fp32 tile in smem, transform.
    __syncthreads();
    float* stg = (float*)smem;
    #pragma unroll
    for (int mi = 0; mi < 4; ++mi)
        #pragma unroll
        for (int nj = 0; nj < NJV; ++nj)
            wmma::store_matrix_sync(stg + (size_t)(warp_m + mi * 16) * 128 + warp_n + nj * 16,
                                    acc[mi][nj], 128, wmma::mem_row_major);
    __syncthreads();

    #pragma unroll
    for (int i = 0; i < TMv / 8; ++i) {
        const int idx = i * NTHR + tid;   // TMv*32 float4 chunks (TMv x 128 fp32)
        const int el = idx * 4;
        const int row = el >> 7;
        const int col = el & 127;
        const float4 v = *(const float4*)(stg + el);
        const size_t m = (size_t)(rowBase + row);
        const int n = colBase + col;
        if (EPI == 1) {
            __half* ChB = Ch + (size_t)blockIdx.z * sC;
            __half* ClB = Cl + (size_t)blockIdx.z * sC;
            const __half h0 = __float2half_rn(v.x), h1 = __float2half_rn(v.y);
            const __half h2 = __float2half_rn(v.z), h3 = __float2half_rn(v.w);
            *(__half2*)(ChB + m * ldc + n)     = __halves2half2(h0, h1);
            *(__half2*)(ChB + m * ldc + n + 2) = __halves2half2(h2, h3);
            *(__half2*)(ClB + m * ldc + n) =
                __halves2half2(__float2half_rn(v.x - __half2float(h0)),
                               __float2half_rn(v.y - __half2float(h1)));
            *(__half2*)(ClB + m * ldc + n + 2) =
                __halves2half2(__float2half_rn(v.z - __half2float(h2)),
                               __float2half_rn(v.w - __half2float(h3)));
        } else if (EPI == 2) {
            __half* ChB = Ch + (size_t)blockIdx.z * sC;
            *(__half2*)(ChB + m * ldc + n)     = __halves2half2(__float2half_rn(v.x), __float2half_rn(v.y));
            *(__half2*)(ChB + m * ldc + n + 2) = __halves2half2(__float2half_rn(v.z), __float2half_rn(v.w));
        } else { // EPI == 3
            const float4 bb = *(const float4*)(bias + n);
            const float4 rr = *(const float4*)(resid + m * ldc + n);
            float4 o;
            o.x = fmaxf(v.x + bb.x, 0.f) + rr.x;
            o.y = fmaxf(v.y + bb.y, 0.f) + rr.y;
            o.z = fmaxf(v.z + bb.z, 0.f) + rr.z;
            o.w = fmaxf(v.w + bb.w, 0.f) + rr.w;
            *(float4*)(Cf + m * ldc + n) = o;
        }
    }
}

// ---------------------------------------------------------------------------
// Fused prep: x -> (xh, xl) and xTh (transpose), one read of x
// ---------------------------------------------------------------------------
__global__ __launch_bounds__(256)
void prep_x_fused(const float* __restrict__ x, __half* __restrict__ xh,
                  __half* __restrict__ xl, __half* __restrict__ xT)
{
    __shared__ float tile[32][33];
    const int b = blockIdx.z;
    const int s0 = blockIdx.x * 32;
    const int d0 = blockIdx.y * 32;
    const float* xb = x + (size_t)b * S * D;
    __half* xtb = xT + (size_t)b * S * D;
    const int tx = threadIdx.x & 31, ty = threadIdx.x >> 5;
    #pragma unroll
    for (int i = 0; i < 32; i += 8) {
        const size_t idx = (size_t)b * S * D + (size_t)(s0 + ty + i) * D + d0 + tx;
        const float v = xb[(size_t)(s0 + ty + i) * D + d0 + tx];
        tile[ty + i][tx] = v;
        const __half h = __float2half_rn(v);
        xh[idx] = h;
        xl[idx] = __float2half_rn(v - __half2float(h));
    }
    __syncthreads();
    #pragma unroll
    for (int i = 0; i < 32; i += 8)
        xtb[(size_t)(d0 + ty + i) * S + s0 + tx] = __float2half_rn(tile[tx][ty + i]);
}

__global__ __launch_bounds__(256)
void prep_w_kernel(const float* __restrict__ W, const float* __restrict__ pw,
                   __half* __restrict__ Wh, __half* __restrict__ Wl, __half* __restrict__ pwh)
{
    const int i = blockIdx.x * 256 + threadIdx.x;
    if (i < D * D) {
        const float v = W[i];
        const __half h = __float2half_rn(v);
        Wh[i] = h;
        Wl[i] = __float2half_rn(v - __half2float(h));
        pwh[i] = __float2half_rn(pw[i]);
    }
}

// ---------------------------------------------------------------------------
// Launch
// ---------------------------------------------------------------------------
extern "C" void kernel_launch(void* const* d_in, const int* in_sizes, int n_in,
                              void* d_out, int out_size)
{
    const float* x  = (const float*)d_in[0];
    const float* W  = (const float*)d_in[1];
    const float* pw = (const float*)d_in[2];
    const float* pb = (const float*)d_in[3];
    float* out = (float*)d_out;

    __half *xh, *xl, *xTh, *Wh, *Wl, *pwh, *Wxh, *Wxl, *ah, *ch;
    float2* st;
    cudaGetSymbolAddress((void**)&xh,  g_xh);
    cudaGetSymbolAddress((void**)&xl,  g_xl);
    cudaGetSymbolAddress((void**)&xTh, g_xTh);
    cudaGetSymbolAddress((void**)&Wh,  g_Wh);
    cudaGetSymbolAddress((void**)&Wl,  g_Wl);
    cudaGetSymbolAddress((void**)&pwh, g_pwh);
    cudaGetSymbolAddress((void**)&Wxh, g_Wxh);
    cudaGetSymbolAddress((void**)&Wxl, g_Wxl);
    cudaGetSymbolAddress((void**)&ah,  g_ah);
    cudaGetSymbolAddress((void**)&ch,  g_ch);
    cudaGetSymbolAddress((void**)&st,  g_st);

    // SP3 (TM=256, 2-stage): 2 x 2*(36864+18432) = 221184
    // PLAIN (TM=128, 2-stage, 2 CTAs/SM): 2 x (18432+18432) = 73728 per CTA
    //   GEMM3 adds 8KB scbuf -> 81920/CTA (2 CTAs = 163840 <= 227KB)
    constexpr uint32_t AT256 = 256 * LDH * 2;
    constexpr int SMEM_SP3 = (int)(2 * 2 * (AT256 + BT_B));      // 221184
    constexpr int SMEM_PL  = (int)(2 * (128 * LDH * 2 + BT_B));  // 73728
    constexpr int SMEM_PLS = SMEM_PL + 128 * NTILE * 4;          // 81920
    cudaFuncSetAttribute(hgemm<true, 1, 256, false>,  cudaFuncAttributeMaxDynamicSharedMemorySize, SMEM_SP3);
    cudaFuncSetAttribute(hgemm<true, 4, 256, false>,  cudaFuncAttributeMaxDynamicSharedMemorySize, SMEM_SP3);
    cudaFuncSetAttribute(hgemm<false, 2, 128, true>,  cudaFuncAttributeMaxDynamicSharedMemorySize, SMEM_PLS);
    cudaFuncSetAttribute(hgemm<false, 3, 128, false>, cudaFuncAttributeMaxDynamicSharedMemorySize, SMEM_PL);

    const size_t SD = (size_t)S * D, SS = (size_t)S * S;

    // prep (x read once: xh, xl, xTh; W/pw tiny)
    prep_x_fused<<<dim3(S / 32, D / 32, B), 256>>>(x, xh, xl, xTh);
    prep_w_kernel<<<(D * D + 255) / 256, 256>>>(W, pw, Wh, Wl, pwh);

    // GEMM1 (fp16x3): Wx = x @ W^T  -> split fp16 (Wxh, Wxl)
    hgemm<true, 1, 256, false><<<dim3(D / TN_CTA, M_TOT / 256, 1), NTHR, SMEM_SP3>>>(
        xh, xl, Wh, Wl, nullptr, Wxh, Wxl, nullptr, nullptr, nullptr,
        D, D, D, D, 0, 0, 0);

    // GEMM2 (fp16x3, batched) + fused partial softmax:
    //   p[b] = exp(masked(Wx[b] @ x[b]^T) - m_tile)  (fp16), stats -> g_st
    hgemm<true, 4, 256, false><<<dim3(S / TN_CTA, S / 256, B), NTHR, SMEM_SP3>>>(
        Wxh, Wxl, xh, xl, nullptr, ah, nullptr, nullptr, nullptr, st,
        D, D, S, D, SD, SD, SS);

    // GEMM3 (fp16, batched, TM=128, 2 CTA/SM, A rescaled in smem by softmax
    //        normalizers — finalize kernel eliminated):
    //   c[b] = softmax(s)[b] @ x[b] -> fp16 ch
    hgemm<false, 2, 128, true><<<dim3(D / TN_CTA, S / 128, B), NTHR, SMEM_PLS>>>(
        ah, nullptr, xTh, nullptr, nullptr, ch, nullptr, nullptr, nullptr, st,
        S, S, D, S, SS, SD, SD);

    // GEMM4 (fp16 + epilogue, TM=128, 2 CTA/SM): out = x + relu(c @ pw^T + pb)
    hgemm<false, 3, 128, false><<<dim3(D / TN_CTA, M_TOT / 128, 1), NTHR, SMEM_PL>>>(
        ch, nullptr, pwh, nullptr, out, nullptr, nullptr, pb, x, nullptr,
        D, D, D, D, 0, 0, 0);
}

// round 16
// speedup vs baseline: 1.0279x; 1.0279x over previous
#include <cuda_runtime.h>
#include <cuda_fp16.h>
#include <mma.h>
#include <cstdint>
#include <math_constants.h>

using namespace nvcuda;

static constexpr int B = 8, S = 2048, D = 768;
static constexpr int M_TOT = B * S;   // 16384
static constexpr int NTILE = S / 128; // 16 key tiles per row

// ---------------------------------------------------------------------------
// Scratch (__device__ globals — allocation-free rule)
// ---------------------------------------------------------------------------
__device__ __half g_xh [(size_t)B * S * D];
__device__ __half g_xl [(size_t)B * S * D];
__device__ __half g_xTh[(size_t)B * S * D];   // [B, D, S]
__device__ __half g_Wh [D * D];
__device__ __half g_Wl [D * D];
__device__ __half g_pwh[D * D];
__device__ __half g_Wxh[(size_t)B * S * D];
__device__ __half g_Wxl[(size_t)B * S * D];
__device__ __half g_ah [(size_t)B * S * S];   // p, then (in place) softmax a, fp16
__device__ __half g_ch [(size_t)B * S * D];
__device__ float2 g_st [(size_t)B * S * NTILE]; // per-(row,tile) partial (max, sumexp)

// ---------------------------------------------------------------------------
// helpers
// ---------------------------------------------------------------------------
__device__ __forceinline__ uint32_t smem_u32(const void* p) {
    uint32_t a;
    asm("{ .reg .u64 t; cvta.to.shared.u64 t, %1; cvt.u32.u64 %0, t; }" : "=r"(a) : "l"(p));
    return a;
}
__device__ __forceinline__ void cp16(uint32_t saddr, const void* g) {
    asm volatile("cp.async.cg.shared.global [%0], [%1], 16;" :: "r"(saddr), "l"(g));
}
__device__ __forceinline__ void cp_commit() { asm volatile("cp.async.commit_group;" ::: "memory"); }
__device__ __forceinline__ void cp_wait1()  { asm volatile("cp.async.wait_group 1;" ::: "memory"); }

__device__ __forceinline__ float wmax(float v) {
    #pragma unroll
    for (int o = 16; o > 0; o >>= 1) v = fmaxf(v, __shfl_xor_sync(0xffffffffu, v, o));
    return v;
}
__device__ __forceinline__ float wsum(float v) {
    #pragma unroll
    for (int o = 16; o > 0; o >>= 1) v += __shfl_xor_sync(0xffffffffu, v, o);
    return v;
}

// ---------------------------------------------------------------------------
// hgemm: C[M,N] = A[M,K] * B[N,K]^T  (both operands K-contiguous fp16)
// 256 threads (8 warps), BK=64, padded smem rows LDH=72 (conflict-free ldsm).
// TMv=256: CTA 256x128, warps 4x2 of 64x64 (acc 4x4)     — SP3 GEMMs, 1 CTA/SM
// TMv=128: CTA 128x128, warps 2x4 of 64x32 (acc 4x2)     — plain GEMMs, 2 CTA/SM
// SP3: 3-pass compensated product (Ah*Bh + Ah*Bl + Al*Bh).
// NST: 2 = double-buffer (2 syncs/chunk); 3 = ring (1 sync/chunk).
// EPI: 1 = split fp16 (Ch+Cl); 2 = fp16 Ch; 3 = fp32 resid + relu(C + bias);
//      4 = fused partial softmax (TMv=256 only)
// ---------------------------------------------------------------------------
static constexpr int BK  = 64;
static constexpr int TN_CTA = 128;
static constexpr int NTHR = 256;
static constexpr int LDH = 72;                        // halves per smem row
static constexpr uint32_t BT_B = TN_CTA * LDH * 2;    // 18432 bytes
static constexpr int LDS4 = 132;                      // fp32 stage stride (EPI4)

template <bool SP3, int TMv>
__device__ __forceinline__ void load_chunk(
    uint32_t sb, const __half* Ah, const __half* Al,
    const __half* Bh, const __half* Bl,
    int lda, int ldb, int rowBase, int colBase, int k0, int tid)
{
    constexpr uint32_t ATB = (uint32_t)TMv * LDH * 2;
    const uint32_t sbB = sb + (SP3 ? 2 : 1) * ATB;
    // A tiles: TMv rows x 8 granules of 16B
    #pragma unroll
    for (int i = 0; i < TMv * 8 / NTHR; ++i) {
        const int g = tid + i * NTHR;
        const int r = g >> 3;
        const int c = g & 7;
        const uint32_t off = (uint32_t)(r * (LDH * 2) + c * 16);
        const size_t ga = (size_t)(rowBase + r) * lda + k0 + c * 8;
        cp16(sb + off, Ah + ga);
        if (SP3) cp16(sb + ATB + off, Al + ga);
    }
    // B tiles: 128 rows x 8 granules = 1024
    #pragma unroll
    for (int i = 0; i < 4; ++i) {
        const int g = tid + i * NTHR;
        const int r = g >> 3;
        const int c = g & 7;
        const uint32_t off = (uint32_t)(r * (LDH * 2) + c * 16);
        const size_t gb = (size_t)(colBase + r) * ldb + k0 + c * 8;
        cp16(sbB + off, Bh + gb);
        if (SP3) cp16(sbB + BT_B + off, Bl + gb);
    }
}

template <bool SP3, int TMv>
__device__ __forceinline__ void compute_chunk(
    const __half* sm,
    wmma::fragment<wmma::accumulator, 16, 16, 16, float> acc[4][4],
    int warp_m, int warp_n)
{
    constexpr int NJV = (TMv == 256) ? 4 : 2;
    const __half* As  = sm;
    const __half* Als = sm + TMv * LDH;
    const __half* Bs  = sm + (SP3 ? 2 : 1) * TMv * LDH;
    const __half* Bls = Bs + TN_CTA * LDH;

    #pragma unroll
    for (int kk = 0; kk < BK / 16; ++kk) {
        wmma::fragment<wmma::matrix_b, 16, 16, 16, __half, wmma::col_major> bh[NJV], bl[NJV];
        wmma::fragment<wmma::matrix_a, 16, 16, 16, __half, wmma::row_major> ah[4], al[4];
        #pragma unroll
        for (int nj = 0; nj < NJV; ++nj) {
            wmma::load_matrix_sync(bh[nj], Bs + (size_t)(warp_n + nj * 16) * LDH + kk * 16, LDH);
            if (SP3)
                wmma::load_matrix_sync(bl[nj], Bls + (size_t)(warp_n + nj * 16) * LDH + kk * 16, LDH);
        }
        #pragma unroll
        for (int mi = 0; mi < 4; ++mi) {
            wmma::load_matrix_sync(ah[mi], As + (size_t)(warp_m + mi * 16) * LDH + kk * 16, LDH);
            if (SP3)
                wmma::load_matrix_sync(al[mi], Als + (size_t)(warp_m + mi * 16) * LDH + kk * 16, LDH);
        }
        #pragma unroll
        for (int mi = 0; mi < 4; ++mi)
            #pragma unroll
            for (int nj = 0; nj < NJV; ++nj)
                wmma::mma_sync(acc[mi][nj], ah[mi], bh[nj], acc[mi][nj]);
        if (SP3) {
            #pragma unroll
            for (int mi = 0; mi < 4; ++mi)
                #pragma unroll
                for (int nj = 0; nj < NJV; ++nj)
                    wmma::mma_sync(acc[mi][nj], ah[mi], bl[nj], acc[mi][nj]);
            #pragma unroll
            for (int mi = 0; mi < 4; ++mi)
                #pragma unroll
                for (int nj = 0; nj < NJV; ++nj)
                    wmma::mma_sync(acc[mi][nj], al[mi], bh[nj], acc[mi][nj]);
        }
    }
}

template <bool SP3, int EPI, int NST, int TMv>
__global__ __launch_bounds__(NTHR, (TMv == 128) ? 2 : 1)
void hgemm(const __half* __restrict__ Ah, const __half* __restrict__ Al,
           const __half* __restrict__ Bh, const __half* __restrict__ Bl,
           float* __restrict__ Cf, __half* __restrict__ Ch, __half* __restrict__ Cl,
           const float* __restrict__ bias, const float* __restrict__ resid,
           float2* __restrict__ stats,
           int lda, int ldb, int ldc, int K,
           size_t sA, size_t sB, size_t sC)
{
    extern __shared__ char smem[];
    const uint32_t sb0 = smem_u32(smem);
    constexpr uint32_t ATB = (uint32_t)TMv * LDH * 2;
    constexpr uint32_t BUF = (SP3 ? 2 : 1) * (ATB + BT_B);
    constexpr int NJV = (TMv == 256) ? 4 : 2;

    const int tid = threadIdx.x, wid = tid >> 5, lane = tid & 31;
    const int rowBase = blockIdx.y * TMv;
    const int colBase = blockIdx.x * TN_CTA;
    // TMv=256: warps 4x2, tiles 64x64.  TMv=128: warps 2x4, tiles 64x32.
    const int warp_m = (TMv == 256) ? (wid >> 1) * 64 : (wid >> 2) * 64;
    const int warp_n = (TMv == 256) ? (wid & 1) * 64  : (wid & 3) * 32;

    Ah += (size_t)blockIdx.z * sA;
    Bh += (size_t)blockIdx.z * sB;
    if (SP3) { Al += (size_t)blockIdx.z * sA; Bl += (size_t)blockIdx.z * sB; }

    wmma::fragment<wmma::accumulator, 16, 16, 16, float> acc[4][4];
    #pragma unroll
    for (int mi = 0; mi < 4; ++mi)
        #pragma unroll
        for (int nj = 0; nj < NJV; ++nj)
            wmma::fill_fragment(acc[mi][nj], 0.0f);

    const int NK = K / BK;

    if (NST == 2) {
        load_chunk<SP3, TMv>(sb0, Ah, Al, Bh, Bl, lda, ldb, rowBase, colBase, 0, tid);
        cp_commit();
        for (int ck = 0; ck < NK; ++ck) {
            if (ck + 1 < NK)
                load_chunk<SP3, TMv>(sb0 + ((ck + 1) & 1) * BUF, Ah, Al, Bh, Bl,
                                     lda, ldb, rowBase, colBase, (ck + 1) * BK, tid);
            cp_commit();
            cp_wait1();
            __syncthreads();
            compute_chunk<SP3, TMv>((const __half*)(smem + (ck & 1) * BUF), acc, warp_m, warp_n);
            __syncthreads();
        }
    } else {
        // 3-stage ring, ONE sync per chunk.
        load_chunk<SP3, TMv>(sb0 + 0 * BUF, Ah, Al, Bh, Bl, lda, ldb, rowBase, colBase, 0, tid);
        cp_commit();
        load_chunk<SP3, TMv>(sb0 + 1 * BUF, Ah, Al, Bh, Bl, lda, ldb, rowBase, colBase, BK, tid);
        cp_commit();
        int wstage = 2, cstage = 0;
        for (int ck = 0; ck < NK; ++ck) {
            cp_wait1();
            __syncthreads();   // stage ck ready; all warps done with stage being overwritten
            if (ck + 2 < NK)
                load_chunk<SP3, TMv>(sb0 + wstage * BUF, Ah, Al, Bh, Bl,
                                     lda, ldb, rowBase, colBase, (ck + 2) * BK, tid);
            cp_commit();       // unconditional: keeps group accounting exact
            compute_chunk<SP3, TMv>((const __half*)(smem + cstage * BUF), acc, warp_m, warp_n);
            wstage = (wstage == 2) ? 0 : wstage + 1;
            cstage = (cstage == 2) ? 0 : cstage + 1;
        }
        __syncthreads();       // protect epilogue smem reuse
    }

    if (EPI == 4) {
        // ---- fused partial softmax (GEMM2, TMv=256) ----
        float* stg = (float*)smem;   // 256 x 128 fp32, stride LDS4=132
        #pragma unroll
        for (int mi = 0; mi < 4; ++mi)
            #pragma unroll
            for (int nj = 0; nj < NJV; ++nj)
                wmma::store_matrix_sync(stg + (size_t)(warp_m + mi * 16) * LDS4 + warp_n + nj * 16,
                                        acc[mi][nj], LDS4, wmma::mem_row_major);
        __syncthreads();

        __half* pB = Ch + (size_t)blockIdx.z * sC;
        #pragma unroll
        for (int rr = 0; rr < 32; ++rr) {
            const int r = wid * 32 + rr;
            const int q = rowBase + r;                 // batch-local query index
            float v[4];
            #pragma unroll
            for (int k = 0; k < 4; ++k) {
                const int c = lane + 32 * k;
                float t = stg[(size_t)r * LDS4 + c];
                if (q == colBase + c) t = -CUDART_INF_F;   // mask diagonal
                v[k] = t;
            }
            float m = fmaxf(fmaxf(v[0], v[1]), fmaxf(v[2], v[3]));
            m = wmax(m);
            float e[4], zs = 0.f;
            #pragma unroll
            for (int k = 0; k < 4; ++k) { e[k] = __expf(v[k] - m); zs += e[k]; }
            const float z = wsum(zs);
            #pragma unroll
            for (int k = 0; k < 4; ++k)
                pB[(size_t)q * ldc + colBase + lane + 32 * k] = __float2half_rn(e[k]);
            if (lane == 0)
                stats[((size_t)blockIdx.z * S + q) * NTILE + (colBase >> 7)] = make_float2(m, z);
        }
        return;
    }

    // staged epilogue (EPI 1/2/3): park the TMv x 128 fp32 tile in smem, transform.
    __syncthreads();
    float* stg = (float*)smem;
    #pragma unroll
    for (int mi = 0; mi < 4; ++mi)
        #pragma unroll
        for (int nj = 0; nj < NJV; ++nj)
            wmma::store_matrix_sync(stg + (size_t)(warp_m + mi * 16) * 128 + warp_n + nj * 16,
                                    acc[mi][nj], 128, wmma::mem_row_major);
    __syncthreads();

    #pragma unroll
    for (int i = 0; i < TMv / 8; ++i) {
        const int idx = i * NTHR + tid;   // TMv*32 float4 chunks (TMv x 128 fp32)
        const int el = idx * 4;
        const int row = el >> 7;
        const int col = el & 127;
        const float4 v = *(const float4*)(stg + el);
        const size_t m = (size_t)(rowBase + row);
        const int n = colBase + col;
        if (EPI == 1) {
            __half* ChB = Ch + (size_t)blockIdx.z * sC;
            __half* ClB = Cl + (size_t)blockIdx.z * sC;
            const __half h0 = __float2half_rn(v.x), h1 = __float2half_rn(v.y);
            const __half h2 = __float2half_rn(v.z), h3 = __float2half_rn(v.w);
            *(__half2*)(ChB + m * ldc + n)     = __halves2half2(h0, h1);
            *(__half2*)(ChB + m * ldc + n + 2) = __halves2half2(h2, h3);
            *(__half2*)(ClB + m * ldc + n) =
                __halves2half2(__float2half_rn(v.x - __half2float(h0)),
                               __float2half_rn(v.y - __half2float(h1)));
            *(__half2*)(ClB + m * ldc + n + 2) =
                __halves2half2(__float2half_rn(v.z - __half2float(h2)),
                               __float2half_rn(v.w - __half2float(h3)));
        } else if (EPI == 2) {
            __half* ChB = Ch + (size_t)blockIdx.z * sC;
            *(__half2*)(ChB + m * ldc + n)     = __halves2half2(__float2half_rn(v.x), __float2half_rn(v.y));
            *(__half2*)(ChB + m * ldc + n + 2) = __halves2half2(__float2half_rn(v.z), __float2half_rn(v.w));
        } else { // EPI == 3
            const float4 bb = *(const float4*)(bias + n);
            const float4 rr = *(const float4*)(resid + m * ldc + n);
            float4 o;
            o.x = fmaxf(v.x + bb.x, 0.f) + rr.x;
            o.y = fmaxf(v.y + bb.y, 0.f) + rr.y;
            o.z = fmaxf(v.z + bb.z, 0.f) + rr.z;
            o.w = fmaxf(v.w + bb.w, 0.f) + rr.w;
            *(float4*)(Cf + m * ldc + n) = o;
        }
    }
}

// ---------------------------------------------------------------------------
// softmax finalize: combine tile stats, rescale p -> a in place (fp16)
// ---------------------------------------------------------------------------
__global__ __launch_bounds__(128)
void softmax_finalize(__half* __restrict__ p, const float2* __restrict__ st)
{
    const size_t row = blockIdx.x;     // 0..B*S-1
    __shared__ float sc[NTILE];
    const int tid = threadIdx.x;

    if (tid == 0) {
        float2 t[NTILE];
        #pragma unroll
        for (int i = 0; i < NTILE; ++i) t[i] = st[row * NTILE + i];
        float M = t[0].x;
        #pragma unroll
        for (int i = 1; i < NTILE; ++i) M = fmaxf(M, t[i].x);
        float Z = 0.f;
        #pragma unroll
        for (int i = 0; i < NTILE; ++i) Z += t[i].y * __expf(t[i].x - M);
        const float inv = 1.0f / Z;
        #pragma unroll
        for (int i = 0; i < NTILE; ++i) sc[i] = __expf(t[i].x - M) * inv;
    }
    __syncthreads();

    __half2* pr = (__half2*)(p + row * S);
    #pragma unroll
    for (int i = tid; i < S / 2; i += 128) {
        const float s = sc[i >> 6];
        const __half2 v = pr[i];
        pr[i] = __floats2half2_rn(__low2float(v) * s, __high2float(v) * s);
    }
}

// ---------------------------------------------------------------------------
// Fused prep: x -> (xh, xl) and xTh (transpose), one read of x
// ---------------------------------------------------------------------------
__global__ __launch_bounds__(256)
void prep_x_fused(const float* __restrict__ x, __half* __restrict__ xh,
                  __half* __restrict__ xl, __half* __restrict__ xT)
{
    __shared__ float tile[32][33];
    const int b = blockIdx.z;
    const int s0 = blockIdx.x * 32;
    const int d0 = blockIdx.y * 32;
    const float* xb = x + (size_t)b * S * D;
    __half* xtb = xT + (size_t)b * S * D;
    const int tx = threadIdx.x & 31, ty = threadIdx.x >> 5;
    #pragma unroll
    for (int i = 0; i < 32; i += 8) {
        const size_t idx = (size_t)b * S * D + (size_t)(s0 + ty + i) * D + d0 + tx;
        const float v = xb[(size_t)(s0 + ty + i) * D + d0 + tx];
        tile[ty + i][tx] = v;
        const __half h = __float2half_rn(v);
        xh[idx] = h;
        xl[idx] = __float2half_rn(v - __half2float(h));
    }
    __syncthreads();
    #pragma unroll
    for (int i = 0; i < 32; i += 8)
        xtb[(size_t)(d0 + ty + i) * S + s0 + tx] = __float2half_rn(tile[tx][ty + i]);
}

__global__ __launch_bounds__(256)
void prep_w_kernel(const float* __restrict__ W, const float* __restrict__ pw,
                   __half* __restrict__ Wh, __half* __restrict__ Wl, __half* __restrict__ pwh)
{
    const int i = blockIdx.x * 256 + threadIdx.x;
    if (i < D * D) {
        const float v = W[i];
        const __half h = __float2half_rn(v);
        Wh[i] = h;
        Wl[i] = __float2half_rn(v - __half2float(h));
        pwh[i] = __float2half_rn(pw[i]);
    }
}

// ---------------------------------------------------------------------------
// Launch
// ---------------------------------------------------------------------------
extern "C" void kernel_launch(void* const* d_in, const int* in_sizes, int n_in,
                              void* d_out, int out_size)
{
    const float* x  = (const float*)d_in[0];
    const float* W  = (const float*)d_in[1];
    const float* pw = (const float*)d_in[2];
    const float* pb = (const float*)d_in[3];
    float* out = (float*)d_out;

    __half *xh, *xl, *xTh, *Wh, *Wl, *pwh, *Wxh, *Wxl, *ah, *ch;
    float2* st;
    cudaGetSymbolAddress((void**)&xh,  g_xh);
    cudaGetSymbolAddress((void**)&xl,  g_xl);
    cudaGetSymbolAddress((void**)&xTh, g_xTh);
    cudaGetSymbolAddress((void**)&Wh,  g_Wh);
    cudaGetSymbolAddress((void**)&Wl,  g_Wl);
    cudaGetSymbolAddress((void**)&pwh, g_pwh);
    cudaGetSymbolAddress((void**)&Wxh, g_Wxh);
    cudaGetSymbolAddress((void**)&Wxl, g_Wxl);
    cudaGetSymbolAddress((void**)&ah,  g_ah);
    cudaGetSymbolAddress((void**)&ch,  g_ch);
    cudaGetSymbolAddress((void**)&st,  g_st);

    // SP3 (TM=256, 2-stage): 2 x 2*(36864+18432) = 221184
    // PLAIN (TM=128, 3-stage ring, 2 CTAs/SM): 3 x (18432+18432) = 110592/CTA
    //   (2 CTAs = 221184 <= 227KB; epilogue stage 65536 <= 110592 OK)
    constexpr uint32_t AT256 = 256 * LDH * 2;
    constexpr int SMEM_SP3 = (int)(2 * 2 * (AT256 + BT_B));      // 221184
    constexpr int SMEM_PL3 = (int)(3 * (128 * LDH * 2 + BT_B));  // 110592
    cudaFuncSetAttribute(hgemm<true, 1, 2, 256>,  cudaFuncAttributeMaxDynamicSharedMemorySize, SMEM_SP3);
    cudaFuncSetAttribute(hgemm<true, 4, 2, 256>,  cudaFuncAttributeMaxDynamicSharedMemorySize, SMEM_SP3);
    cudaFuncSetAttribute(hgemm<false, 2, 3, 128>, cudaFuncAttributeMaxDynamicSharedMemorySize, SMEM_PL3);
    cudaFuncSetAttribute(hgemm<false, 3, 3, 128>, cudaFuncAttributeMaxDynamicSharedMemorySize, SMEM_PL3);

    const size_t SD = (size_t)S * D, SS = (size_t)S * S;

    // prep (x read once: xh, xl, xTh; W/pw tiny)
    prep_x_fused<<<dim3(S / 32, D / 32, B), 256>>>(x, xh, xl, xTh);
    prep_w_kernel<<<(D * D + 255) / 256, 256>>>(W, pw, Wh, Wl, pwh);

    // GEMM1 (fp16x3): Wx = x @ W^T  -> split fp16 (Wxh, Wxl)
    hgemm<true, 1, 2, 256><<<dim3(D / TN_CTA, M_TOT / 256, 1), NTHR, SMEM_SP3>>>(
        xh, xl, Wh, Wl, nullptr, Wxh, Wxl, nullptr, nullptr, nullptr,
        D, D, D, D, 0, 0, 0);

    // GEMM2 (fp16x3, batched) + fused partial softmax:
    //   p[b] = exp(masked(Wx[b] @ x[b]^T) - m_tile)  (fp16), stats -> g_st
    hgemm<true, 4, 2, 256><<<dim3(S / TN_CTA, S / 256, B), NTHR, SMEM_SP3>>>(
        Wxh, Wxl, xh, xl, nullptr, ah, nullptr, nullptr, nullptr, st,
        D, D, S, D, SD, SD, SS);

    // combine tile stats, rescale p -> a in place
    softmax_finalize<<<B * S, 128>>>(ah, st);

    // GEMM3 (fp16, batched, TM=128, ring, 2 CTA/SM): c[b] = a[b] @ x[b] -> ch
    hgemm<false, 2, 3, 128><<<dim3(D / TN_CTA, S / 128, B), NTHR, SMEM_PL3>>>(
        ah, nullptr, xTh, nullptr, nullptr, ch, nullptr, nullptr, nullptr, nullptr,
        S, S, D, S, SS, SD, SD);

    // GEMM4 (fp16 + epilogue, TM=128, ring, 2 CTA/SM): out = x + relu(c @ pw^T + pb)
    hgemm<false, 3, 3, 128><<<dim3(D / TN_CTA, M_TOT / 128, 1), NTHR, SMEM_PL3>>>(
        ch, nullptr, pwh, nullptr, out, nullptr, nullptr, pb, x, nullptr,
        D, D, D, D, 0, 0, 0);
}

// round 17
// speedup vs baseline: 1.0351x; 1.0070x over previous
#include <cuda_runtime.h>
#include <cuda_fp16.h>
#include <mma.h>
#include <cstdint>
#include <math_constants.h>

using namespace nvcuda;

static constexpr int B = 8, S = 2048, D = 768;
static constexpr int M_TOT = B * S;   // 16384
static constexpr int NTILE = S / 128; // 16 key tiles per row

// ---------------------------------------------------------------------------
// Scratch (__device__ globals — allocation-free rule)
// ---------------------------------------------------------------------------
__device__ __half g_xh [(size_t)B * S * D];
__device__ __half g_xl [(size_t)B * S * D];
__device__ __half g_xTh[(size_t)B * S * D];   // [B, D, S]
__device__ __half g_Wh [D * D];
__device__ __half g_Wl [D * D];
__device__ __half g_pwh[D * D];
__device__ __half g_Wxh[(size_t)B * S * D];
__device__ __half g_Wxl[(size_t)B * S * D];
__device__ __half g_ah [(size_t)B * S * S];   // p, then (in place) softmax a, fp16
__device__ __half g_ch [(size_t)B * S * D];
__device__ float2 g_st [(size_t)B * S * NTILE]; // per-(row,tile) partial (max, sumexp)

// ---------------------------------------------------------------------------
// helpers
// ---------------------------------------------------------------------------
__device__ __forceinline__ uint32_t smem_u32(const void* p) {
    uint32_t a;
    asm("{ .reg .u64 t; cvta.to.shared.u64 t, %1; cvt.u32.u64 %0, t; }" : "=r"(a) : "l"(p));
    return a;
}
__device__ __forceinline__ void cp16(uint32_t saddr, const void* g) {
    asm volatile("cp.async.cg.shared.global [%0], [%1], 16;" :: "r"(saddr), "l"(g));
}
__device__ __forceinline__ void cp_commit() { asm volatile("cp.async.commit_group;" ::: "memory"); }
__device__ __forceinline__ void cp_wait1()  { asm volatile("cp.async.wait_group 1;" ::: "memory"); }

__device__ __forceinline__ float wmax(float v) {
    #pragma unroll
    for (int o = 16; o > 0; o >>= 1) v = fmaxf(v, __shfl_xor_sync(0xffffffffu, v, o));
    return v;
}
__device__ __forceinline__ float wsum(float v) {
    #pragma unroll
    for (int o = 16; o > 0; o >>= 1) v += __shfl_xor_sync(0xffffffffu, v, o);
    return v;
}

// ---------------------------------------------------------------------------
// hgemm: C[M,N] = A[M,K] * B[N,K]^T  (both operands K-contiguous fp16)
// 256 threads (8 warps), BK=64, padded smem rows LDH=72 (conflict-free ldsm).
// TMv=256: CTA 256x128, warps 4x2 of 64x64 (acc 4x4)     — SP3 GEMMs, 1 CTA/SM
// TMv=128: CTA 128x128, warps 2x4 of 64x32 (acc 4x2)     — plain GEMMs, 2 CTA/SM
// SP3: 3-pass compensated product (Ah*Bh + Ah*Bl + Al*Bh).
// EPI: 1 = split fp16 (Ch+Cl); 2 = fp16 Ch; 3 = fp32 resid + relu(C + bias);
//      4 = fused partial softmax (TMv=256 only)
// ---------------------------------------------------------------------------
static constexpr int BK  = 64;
static constexpr int TN_CTA = 128;
static constexpr int NTHR = 256;
static constexpr int LDH = 72;                        // halves per smem row
static constexpr uint32_t BT_B = TN_CTA * LDH * 2;    // 18432 bytes
static constexpr int LDS4 = 132;                      // fp32 stage stride (EPI4)

template <bool SP3, int TMv>
__device__ __forceinline__ void load_chunk(
    uint32_t sb, const __half* Ah, const __half* Al,
    const __half* Bh, const __half* Bl,
    int lda, int ldb, int rowBase, int colBase, int k0, int tid)
{
    constexpr uint32_t ATB = (uint32_t)TMv * LDH * 2;
    const uint32_t sbB = sb + (SP3 ? 2 : 1) * ATB;
    // A tiles: TMv rows x 8 granules of 16B
    #pragma unroll
    for (int i = 0; i < TMv * 8 / NTHR; ++i) {
        const int g = tid + i * NTHR;
        const int r = g >> 3;
        const int c = g & 7;
        const uint32_t off = (uint32_t)(r * (LDH * 2) + c * 16);
        const size_t ga = (size_t)(rowBase + r) * lda + k0 + c * 8;
        cp16(sb + off, Ah + ga);
        if (SP3) cp16(sb + ATB + off, Al + ga);
    }
    // B tiles: 128 rows x 8 granules = 1024
    #pragma unroll
    for (int i = 0; i < 4; ++i) {
        const int g = tid + i * NTHR;
        const int r = g >> 3;
        const int c = g & 7;
        const uint32_t off = (uint32_t)(r * (LDH * 2) + c * 16);
        const size_t gb = (size_t)(colBase + r) * ldb + k0 + c * 8;
        cp16(sbB + off, Bh + gb);
        if (SP3) cp16(sbB + BT_B + off, Bl + gb);
    }
}

template <bool SP3, int TMv>
__device__ __forceinline__ void compute_chunk(
    const __half* sm,
    wmma::fragment<wmma::accumulator, 16, 16, 16, float> acc[4][4],
    int warp_m, int warp_n)
{
    constexpr int NJV = (TMv == 256) ? 4 : 2;
    const __half* As  = sm;
    const __half* Als = sm + TMv * LDH;
    const __half* Bs  = sm + (SP3 ? 2 : 1) * TMv * LDH;
    const __half* Bls = Bs + TN_CTA * LDH;

    #pragma unroll
    for (int kk = 0; kk < BK / 16; ++kk) {
        wmma::fragment<wmma::matrix_b, 16, 16, 16, __half, wmma::col_major> bh[NJV], bl[NJV];
        wmma::fragment<wmma::matrix_a, 16, 16, 16, __half, wmma::row_major> ah[4], al[4];
        #pragma unroll
        for (int nj = 0; nj < NJV; ++nj) {
            wmma::load_matrix_sync(bh[nj], Bs + (size_t)(warp_n + nj * 16) * LDH + kk * 16, LDH);
            if (SP3)
                wmma::load_matrix_sync(bl[nj], Bls + (size_t)(warp_n + nj * 16) * LDH + kk * 16, LDH);
        }
        #pragma unroll
        for (int mi = 0; mi < 4; ++mi) {
            wmma::load_matrix_sync(ah[mi], As + (size_t)(warp_m + mi * 16) * LDH + kk * 16, LDH);
            if (SP3)
                wmma::load_matrix_sync(al[mi], Als + (size_t)(warp_m + mi * 16) * LDH + kk * 16, LDH);
        }
        #pragma unroll
        for (int mi = 0; mi < 4; ++mi)
            #pragma unroll
            for (int nj = 0; nj < NJV; ++nj)
                wmma::mma_sync(acc[mi][nj], ah[mi], bh[nj], acc[mi][nj]);
        if (SP3) {
            #pragma unroll
            for (int mi = 0; mi < 4; ++mi)
                #pragma unroll
                for (int nj = 0; nj < NJV; ++nj)
                    wmma::mma_sync(acc[mi][nj], ah[mi], bl[nj], acc[mi][nj]);
            #pragma unroll
            for (int mi = 0; mi < 4; ++mi)
                #pragma unroll
                for (int nj = 0; nj < NJV; ++nj)
                    wmma::mma_sync(acc[mi][nj], al[mi], bh[nj], acc[mi][nj]);
        }
    }
}

template <bool SP3, int EPI, int TMv>
__global__ __launch_bounds__(NTHR, (TMv == 128) ? 2 : 1)
void hgemm(const __half* __restrict__ Ah, const __half* __restrict__ Al,
           const __half* __restrict__ Bh, const __half* __restrict__ Bl,
           float* __restrict__ Cf, __half* __restrict__ Ch, __half* __restrict__ Cl,
           const float* __restrict__ bias, const float* __restrict__ resid,
           float2* __restrict__ stats,
           int lda, int ldb, int ldc, int K,
           size_t sA, size_t sB, size_t sC)
{
    extern __shared__ char smem[];
    const uint32_t sb0 = smem_u32(smem);
    constexpr uint32_t ATB = (uint32_t)TMv * LDH * 2;
    constexpr uint32_t BUF = (SP3 ? 2 : 1) * (ATB + BT_B);
    constexpr int NJV = (TMv == 256) ? 4 : 2;

    const int tid = threadIdx.x, wid = tid >> 5, lane = tid & 31;
    const int rowBase = blockIdx.y * TMv;
    const int colBase = blockIdx.x * TN_CTA;
    // TMv=256: warps 4x2, tiles 64x64.  TMv=128: warps 2x4, tiles 64x32.
    const int warp_m = (TMv == 256) ? (wid >> 1) * 64 : (wid >> 2) * 64;
    const int warp_n = (TMv == 256) ? (wid & 1) * 64  : (wid & 3) * 32;

    Ah += (size_t)blockIdx.z * sA;
    Bh += (size_t)blockIdx.z * sB;
    if (SP3) { Al += (size_t)blockIdx.z * sA; Bl += (size_t)blockIdx.z * sB; }

    wmma::fragment<wmma::accumulator, 16, 16, 16, float> acc[4][4];
    #pragma unroll
    for (int mi = 0; mi < 4; ++mi)
        #pragma unroll
        for (int nj = 0; nj < NJV; ++nj)
            wmma::fill_fragment(acc[mi][nj], 0.0f);

    const int NK = K / BK;

    load_chunk<SP3, TMv>(sb0, Ah, Al, Bh, Bl, lda, ldb, rowBase, colBase, 0, tid);
    cp_commit();

    for (int ck = 0; ck < NK; ++ck) {
        if (ck + 1 < NK)
            load_chunk<SP3, TMv>(sb0 + ((ck + 1) & 1) * BUF, Ah, Al, Bh, Bl,
                                 lda, ldb, rowBase, colBase, (ck + 1) * BK, tid);
        cp_commit();
        cp_wait1();
        __syncthreads();
        compute_chunk<SP3, TMv>((const __half*)(smem + (ck & 1) * BUF), acc, warp_m, warp_n);
        __syncthreads();
    }

    if (EPI == 4) {
        // ---- fused partial softmax (GEMM2, TMv=256) ----
        float* stg = (float*)smem;   // 256 x 128 fp32, stride LDS4=132
        #pragma unroll
        for (int mi = 0; mi < 4; ++mi)
            #pragma unroll
            for (int nj = 0; nj < NJV; ++nj)
                wmma::store_matrix_sync(stg + (size_t)(warp_m + mi * 16) * LDS4 + warp_n + nj * 16,
                                        acc[mi][nj], LDS4, wmma::mem_row_major);
        __syncthreads();

        __half* pB = Ch + (size_t)blockIdx.z * sC;
        // warp wid reduces rows [wid*32, wid*32+32); lanes own column PAIRS
        #pragma unroll
        for (int rr = 0; rr < 32; ++rr) {
            const int r = wid * 32 + rr;
            const int q = rowBase + r;                 // batch-local query index
            float v[4];
            #pragma unroll
            for (int k = 0; k < 2; ++k) {
                const int c = 2 * lane + 64 * k;       // column pair base
                const float2 t2 = *(const float2*)(stg + (size_t)r * LDS4 + c);
                v[2 * k + 0] = (q == colBase + c)     ? -CUDART_INF_F : t2.x;
                v[2 * k + 1] = (q == colBase + c + 1) ? -CUDART_INF_F : t2.y;
            }
            float m = fmaxf(fmaxf(v[0], v[1]), fmaxf(v[2], v[3]));
            m = wmax(m);
            float e[4], zs = 0.f;
            #pragma unroll
            for (int k = 0; k < 4; ++k) { e[k] = __expf(v[k] - m); zs += e[k]; }
            const float z = wsum(zs);
            #pragma unroll
            for (int k = 0; k < 2; ++k)
                *(__half2*)(pB + (size_t)q * ldc + colBase + 2 * lane + 64 * k) =
                    __floats2half2_rn(e[2 * k], e[2 * k + 1]);
            if (lane == 0)
                stats[((size_t)blockIdx.z * S + q) * NTILE + (colBase >> 7)] = make_float2(m, z);
        }
        return;
    }

    // staged epilogue (EPI 1/2/3): park the TMv x 128 fp32 tile in smem, transform.
    __syncthreads();
    float* stg = (float*)smem;
    #pragma unroll
    for (int mi = 0; mi < 4; ++mi)
        #pragma unroll
        for (int nj = 0; nj < NJV; ++nj)
            wmma::store_matrix_sync(stg + (size_t)(warp_m + mi * 16) * 128 + warp_n + nj * 16,
                                    acc[mi][nj], 128, wmma::mem_row_major);
    __syncthreads();

    #pragma unroll
    for (int i = 0; i < TMv / 8; ++i) {
        const int idx = i * NTHR + tid;   // TMv*32 float4 chunks (TMv x 128 fp32)
        const int el = idx * 4;
        const int row = el >> 7;
        const int col = el & 127;
        const float4 v = *(const float4*)(stg + el);
        const size_t m = (size_t)(rowBase + row);
        const int n = colBase + col;
        if (EPI == 1) {
            __half* ChB = Ch + (size_t)blockIdx.z * sC;
            __half* ClB = Cl + (size_t)blockIdx.z * sC;
            const __half h0 = __float2half_rn(v.x), h1 = __float2half_rn(v.y);
            const __half h2 = __float2half_rn(v.z), h3 = __float2half_rn(v.w);
            *(__half2*)(ChB + m * ldc + n)     = __halves2half2(h0, h1);
            *(__half2*)(ChB + m * ldc + n + 2) = __halves2half2(h2, h3);
            *(__half2*)(ClB + m * ldc + n) =
                __halves2half2(__float2half_rn(v.x - __half2float(h0)),
                               __float2half_rn(v.y - __half2float(h1)));
            *(__half2*)(ClB + m * ldc + n + 2) =
                __halves2half2(__float2half_rn(v.z - __half2float(h2)),
                               __float2half_rn(v.w - __half2float(h3)));
        } else if (EPI == 2) {
            __half* ChB = Ch + (size_t)blockIdx.z * sC;
            *(__half2*)(ChB + m * ldc + n)     = __halves2half2(__float2half_rn(v.x), __float2half_rn(v.y));
            *(__half2*)(ChB + m * ldc + n + 2) = __halves2half2(__float2half_rn(v.z), __float2half_rn(v.w));
        } else { // EPI == 3
            const float4 bb = *(const float4*)(bias + n);
            const float4 rr = *(const float4*)(resid + m * ldc + n);
            float4 o;
            o.x = fmaxf(v.x + bb.x, 0.f) + rr.x;
            o.y = fmaxf(v.y + bb.y, 0.f) + rr.y;
            o.z = fmaxf(v.z + bb.z, 0.f) + rr.z;
            o.w = fmaxf(v.w + bb.w, 0.f) + rr.w;
            *(float4*)(Cf + m * ldc + n) = o;
        }
    }
}

// ---------------------------------------------------------------------------
// softmax finalize: combine tile stats, rescale p -> a in place (fp16)
// 4 rows per 256-thread block; scales computed by 64 parallel threads.
// ---------------------------------------------------------------------------
__global__ __launch_bounds__(256)
void softmax_finalize(__half* __restrict__ p, const float2* __restrict__ st)
{
    __shared__ float sc[4][NTILE];
    const int tid = threadIdx.x;
    const size_t row0 = (size_t)blockIdx.x * 4;

    if (tid < 64) {
        const int rloc = tid >> 4;          // 0..3
        const int i = tid & 15;             // ktile
        const float2* strow = st + (row0 + rloc) * NTILE;
        float2 t[NTILE];
        #pragma unroll
        for (int j = 0; j < NTILE; ++j) t[j] = strow[j];
        float M = t[0].x;
        #pragma unroll
        for (int j = 1; j < NTILE; ++j) M = fmaxf(M, t[j].x);
        float Z = 0.f;
        #pragma unroll
        for (int j = 0; j < NTILE; ++j) Z += t[j].y * __expf(t[j].x - M);
        sc[rloc][i] = __expf(t[i].x - M) * (1.0f / Z);
    }
    __syncthreads();

    const int rloc = tid >> 6;              // 0..3
    const int j = tid & 63;
    __half2* pr = (__half2*)(p + (row0 + rloc) * S);
    #pragma unroll
    for (int i = j; i < S / 2; i += 64) {
        const float s = sc[rloc][i >> 6];   // (2*i)/128
        const __half2 v = pr[i];
        pr[i] = __floats2half2_rn(__low2float(v) * s, __high2float(v) * s);
    }
}

// ---------------------------------------------------------------------------
// Fused prep: x -> (xh, xl) and xTh (transpose), one read of x
// ---------------------------------------------------------------------------
__global__ __launch_bounds__(256)
void prep_x_fused(const float* __restrict__ x, __half* __restrict__ xh,
                  __half* __restrict__ xl, __half* __restrict__ xT)
{
    __shared__ float tile[32][33];
    const int b = blockIdx.z;
    const int s0 = blockIdx.x * 32;
    const int d0 = blockIdx.y * 32;
    const float* xb = x + (size_t)b * S * D;
    __half* xtb = xT + (size_t)b * S * D;
    const int tx = threadIdx.x & 31, ty = threadIdx.x >> 5;
    #pragma unroll
    for (int i = 0; i < 32; i += 8) {
        const size_t idx = (size_t)b * S * D + (size_t)(s0 + ty + i) * D + d0 + tx;
        const float v = xb[(size_t)(s0 + ty + i) * D + d0 + tx];
        tile[ty + i][tx] = v;
        const __half h = __float2half_rn(v);
        xh[idx] = h;
        xl[idx] = __float2half_rn(v - __half2float(h));
    }
    __syncthreads();
    #pragma unroll
    for (int i = 0; i < 32; i += 8)
        xtb[(size_t)(d0 + ty + i) * S + s0 + tx] = __float2half_rn(tile[tx][ty + i]);
}

__global__ __launch_bounds__(256)
void prep_w_kernel(const float* __restrict__ W, const float* __restrict__ pw,
                   __half* __restrict__ Wh, __half* __restrict__ Wl, __half* __restrict__ pwh)
{
    const int i = blockIdx.x * 256 + threadIdx.x;
    if (i < D * D) {
        const float v = W[i];
        const __half h = __float2half_rn(v);
        Wh[i] = h;
        Wl[i] = __float2half_rn(v - __half2float(h));
        pwh[i] = __float2half_rn(pw[i]);
    }
}

// ---------------------------------------------------------------------------
// Launch
// ---------------------------------------------------------------------------
extern "C" void kernel_launch(void* const* d_in, const int* in_sizes, int n_in,
                              void* d_out, int out_size)
{
    const float* x  = (const float*)d_in[0];
    const float* W  = (const float*)d_in[1];
    const float* pw = (const float*)d_in[2];
    const float* pb = (const float*)d_in[3];
    float* out = (float*)d_out;

    __half *xh, *xl, *xTh, *Wh, *Wl, *pwh, *Wxh, *Wxl, *ah, *ch;
    float2* st;
    cudaGetSymbolAddress((void**)&xh,  g_xh);
    cudaGetSymbolAddress((void**)&xl,  g_xl);
    cudaGetSymbolAddress((void**)&xTh, g_xTh);
    cudaGetSymbolAddress((void**)&Wh,  g_Wh);
    cudaGetSymbolAddress((void**)&Wl,  g_Wl);
    cudaGetSymbolAddress((void**)&pwh, g_pwh);
    cudaGetSymbolAddress((void**)&Wxh, g_Wxh);
    cudaGetSymbolAddress((void**)&Wxl, g_Wxl);
    cudaGetSymbolAddress((void**)&ah,  g_ah);
    cudaGetSymbolAddress((void**)&ch,  g_ch);
    cudaGetSymbolAddress((void**)&st,  g_st);

    // SP3 (TM=256, 2-stage): 2 x 2*(36864+18432) = 221184
    // PLAIN (TM=128, 2-stage, 2 CTAs/SM): 2 x (18432+18432) = 73728 per CTA
    //   (epilogue stage 128*128*4 = 65536 <= 73728 OK; 2 CTAs = 147456 <= 227KB)
    constexpr uint32_t AT256 = 256 * LDH * 2;
    constexpr int SMEM_SP3 = (int)(2 * 2 * (AT256 + BT_B));     // 221184
    constexpr int SMEM_PL  = (int)(2 * (128 * LDH * 2 + BT_B)); // 73728
    cudaFuncSetAttribute(hgemm<true, 1, 256>,  cudaFuncAttributeMaxDynamicSharedMemorySize, SMEM_SP3);
    cudaFuncSetAttribute(hgemm<true, 4, 256>,  cudaFuncAttributeMaxDynamicSharedMemorySize, SMEM_SP3);
    cudaFuncSetAttribute(hgemm<false, 2, 128>, cudaFuncAttributeMaxDynamicSharedMemorySize, SMEM_PL);
    cudaFuncSetAttribute(hgemm<false, 3, 128>, cudaFuncAttributeMaxDynamicSharedMemorySize, SMEM_PL);

    const size_t SD = (size_t)S * D, SS = (size_t)S * S;

    // prep (x read once: xh, xl, xTh; W/pw tiny)
    prep_x_fused<<<dim3(S / 32, D / 32, B), 256>>>(x, xh, xl, xTh);
    prep_w_kernel<<<(D * D + 255) / 256, 256>>>(W, pw, Wh, Wl, pwh);

    // GEMM1 (fp16x3): Wx = x @ W^T  -> split fp16 (Wxh, Wxl)
    hgemm<true, 1, 256><<<dim3(D / TN_CTA, M_TOT / 256, 1), NTHR, SMEM_SP3>>>(
        xh, xl, Wh, Wl, nullptr, Wxh, Wxl, nullptr, nullptr, nullptr,
        D, D, D, D, 0, 0, 0);

    // GEMM2 (fp16x3, batched) + fused partial softmax:
    //   p[b] = exp(masked(Wx[b] @ x[b]^T) - m_tile)  (fp16), stats -> g_st
    hgemm<true, 4, 256><<<dim3(S / TN_CTA, S / 256, B), NTHR, SMEM_SP3>>>(
        Wxh, Wxl, xh, xl, nullptr, ah, nullptr, nullptr, nullptr, st,
        D, D, S, D, SD, SD, SS);

    // combine tile stats, rescale p -> a in place (4 rows per block)
    softmax_finalize<<<M_TOT / 4, 256>>>(ah, st);

    // GEMM3 (fp16, batched, TM=128, 2 CTA/SM): c[b] = a[b] @ x[b] -> fp16 ch
    hgemm<false, 2, 128><<<dim3(D / TN_CTA, S / 128, B), NTHR, SMEM_PL>>>(
        ah, nullptr, xTh, nullptr, nullptr, ch, nullptr, nullptr, nullptr, nullptr,
        S, S, D, S, SS, SD, SD);

    // GEMM4 (fp16 + epilogue, TM=128, 2 CTA/SM): out = x + relu(c @ pw^T + pb)
    hgemm<false, 3, 128><<<dim3(D / TN_CTA, M_TOT / 128, 1), NTHR, SMEM_PL>>>(
        ch, nullptr, pwh, nullptr, out, nullptr, nullptr, pb, x, nullptr,
        D, D, D, D, 0, 0, 0);
}